// round 1
// baseline (speedup 1.0000x reference)
#include <cuda_runtime.h>
#include <cuda_fp16.h>

// out[b,o] = max_i min(x[b,i], w[i,o])   (STE forward == hard max)
// x: [B,512] f32, w: [512,512] f32, out: [B,512] f32. B = 1024.
//
// fp16x2 packed min/max (HMNMX2): two K-lanes per register, halving the
// dominant-pipe op count vs fp32 FMNMX. Inputs in [0,1) so fp16 rel err
// <= ~5e-4 << 1e-3 tolerance, and min/max are exact selections.

#define KDIM 512
#define ODIM 512
#define TB 64          // batch tile
#define TO 32          // output tile
#define TK 128         // k chunk (elements)
#define TK2 (TK / 2)   // k chunk in half2 (64)
#define NTHREADS 256

__global__ __launch_bounds__(NTHREADS)
void smooth_ste_maxmin_kernel(const float* __restrict__ x,
                              const float* __restrict__ w,
                              float* __restrict__ out)
{
    // xs[b][k2]: +1 pad -> 260B row stride -> consecutive b rows land on
    // adjacent banks (65 mod 32 == 1): conflict-free 4-row reads.
    __shared__ __half2 xs[TB][TK2 + 1];
    __shared__ __half2 ws[TK2][TO];

    const int tid = threadIdx.x;
    const int tx  = tid & 15;   // o sub-tile (2 outputs)
    const int ty  = tid >> 4;   // b sub-tile (4 batches)
    const int oB  = blockIdx.x * TO;
    const int bB  = blockIdx.y * TB;

    __half2 acc[4][2];
#pragma unroll
    for (int j = 0; j < 4; j++) {
        acc[j][0] = __float2half2_rn(0.f);   // inputs >= 0, so 0 is a safe -inf
        acc[j][1] = __float2half2_rn(0.f);
    }

    for (int k0 = 0; k0 < KDIM; k0 += TK) {
        // ---- stage x tile: TB rows x TK2 half2 (4096 entries, 16/thread) ----
#pragma unroll
        for (int t = 0; t < (TB * TK2) / NTHREADS; t++) {
            int idx = tid + t * NTHREADS;
            int b   = idx >> 6;        // / TK2
            int k2  = idx & (TK2 - 1);
            float2 v = *reinterpret_cast<const float2*>(
                &x[(size_t)(bB + b) * KDIM + k0 + 2 * k2]);
            xs[b][k2] = __floats2half2_rn(v.x, v.y);
        }
        // ---- stage w tile: TK2 x TO half2 (2048 entries, 8/thread) ----
#pragma unroll
        for (int t = 0; t < (TK2 * TO) / NTHREADS; t++) {
            int idx = tid + t * NTHREADS;
            int o   = idx & (TO - 1);
            int k2  = idx >> 5;
            float w0 = w[(size_t)(k0 + 2 * k2)     * ODIM + oB + o];
            float w1 = w[(size_t)(k0 + 2 * k2 + 1) * ODIM + oB + o];
            ws[k2][o] = __floats2half2_rn(w0, w1);
        }
        __syncthreads();

        // ---- main loop: per k2 step, 6 LDS + 16 HMNMX2 for 16 outputs ----
#pragma unroll 16
        for (int k2 = 0; k2 < TK2; k2++) {
            __half2 wv0 = ws[k2][2 * tx];
            __half2 wv1 = ws[k2][2 * tx + 1];
#pragma unroll
            for (int j = 0; j < 4; j++) {
                __half2 xv = xs[ty * 4 + j][k2];
                acc[j][0] = __hmax2(acc[j][0], __hmin2(xv, wv0));
                acc[j][1] = __hmax2(acc[j][1], __hmin2(xv, wv1));
            }
        }
        __syncthreads();
    }

    // ---- epilogue: reduce the two packed K-lanes, store f32 ----
#pragma unroll
    for (int j = 0; j < 4; j++) {
        int b = bB + ty * 4 + j;
#pragma unroll
        for (int q = 0; q < 2; q++) {
            __half2 a = acc[j][q];
            float r = fmaxf(__low2float(a), __high2float(a));
            out[(size_t)b * ODIM + oB + 2 * tx + q] = r;
        }
    }
}

extern "C" void kernel_launch(void* const* d_in, const int* in_sizes, int n_in,
                              void* d_out, int out_size)
{
    const float* x = (const float*)d_in[0];      // [B, 512]
    const float* w = (const float*)d_in[1];      // [512, 512]
    float* out = (float*)d_out;                  // [B, 512]

    int B = in_sizes[0] / KDIM;                  // 1024

    dim3 grid(ODIM / TO, B / TB);                // (16, 16) = 256 blocks
    smooth_ste_maxmin_kernel<<<grid, NTHREADS>>>(x, w, out);
}

// round 2
// speedup vs baseline: 1.3319x; 1.3319x over previous
#include <cuda_runtime.h>
#include <cuda_fp16.h>

// out[b,o] = max_k min(x[b,k], w[k,o])  (STE forward == hard max-min)
// x: [1024,512] f32, w: [512,512] f32, out f32.
//
// Strategy: fp16x2 packed min/max (HMNMX2, alu pipe, rt_SMSP=2).
// Prepack kernel converts x,w to half2 (packed along k) into __device__
// scratch. Main kernel: per CTA stage full-K tiles (64 b x 512 k, 512 k x
// 32 o) in smem once (single barrier), then 256 k2 steps of
// 3 LDS + 8 HMNMX2 per thread (4 outputs/thread -> 4096 warps for latency
// hiding).

#define KDIM 512
#define ODIM 512
#define K2   256          // KDIM/2 (half2 units)
#define BMAX 1024
#define TB   64
#define TO   32
#define NT   512

__device__ __half2 g_xh[BMAX * K2];   // [b][k2]
__device__ __half2 g_wh[K2 * ODIM];   // [k2][o]

__global__ void prepack_kernel(const float* __restrict__ x,
                               const float* __restrict__ w, int B)
{
    int i = blockIdx.x * blockDim.x + threadIdx.x;
    int nx = B * K2;
    if (i < nx) {
        float2 v = reinterpret_cast<const float2*>(x)[i];
        g_xh[i] = __floats2half2_rn(v.x, v.y);
    }
    if (i < K2 * ODIM) {
        int k2 = i >> 9;          // / ODIM
        int o  = i & (ODIM - 1);
        float w0 = w[(size_t)(2 * k2)     * ODIM + o];
        float w1 = w[(size_t)(2 * k2 + 1) * ODIM + o];
        g_wh[i] = __floats2half2_rn(w0, w1);
    }
}

__global__ __launch_bounds__(NT)
void maxmin_main_kernel(float* __restrict__ out)
{
    extern __shared__ __half2 smem[];
    __half2* xs = smem;              // [TB][K2]  (64 KB) contiguous slice of g_xh
    __half2* ws = smem + TB * K2;    // [K2][TO]  (32 KB)

    const int tid = threadIdx.x;
    const int tx  = tid & 15;        // -> outputs 2tx, 2tx+1
    const int ty  = tid >> 4;        // -> batches 2ty, 2ty+1
    const int oB  = blockIdx.x * TO;
    const int bB  = blockIdx.y * TB;

    // ---- stage x: contiguous 64KB copy (rows bB..bB+63, full K) ----
    {
        const uint4* src = reinterpret_cast<const uint4*>(g_xh + (size_t)bB * K2);
        uint4* dst = reinterpret_cast<uint4*>(xs);
#pragma unroll
        for (int i = tid; i < TB * K2 / 4; i += NT) dst[i] = src[i];
    }
    // ---- stage w: 256 rows x 128B each from g_wh[k2][oB..oB+31] ----
    {
        uint4* dst = reinterpret_cast<uint4*>(ws);
#pragma unroll
        for (int i = tid; i < K2 * (TO / 4); i += NT) {
            int k2 = i >> 3;
            int c  = i & 7;
            dst[i] = reinterpret_cast<const uint4*>(g_wh + (size_t)k2 * ODIM + oB)[c];
        }
    }
    __syncthreads();

    __half2 a00 = __float2half2_rn(0.f);   // inputs >= 0: 0 is a safe -inf
    __half2 a01 = __float2half2_rn(0.f);
    __half2 a10 = __float2half2_rn(0.f);
    __half2 a11 = __float2half2_rn(0.f);

    const __half2* xr0 = xs + (size_t)(2 * ty) * K2;
    const __half2* xr1 = xs + (size_t)(2 * ty + 1) * K2;
    const unsigned long long* wp =
        reinterpret_cast<const unsigned long long*>(ws + 2 * tx);

#pragma unroll 16
    for (int k2 = 0; k2 < K2; k2++) {
        unsigned long long wbits = wp[k2 * (TO / 2)];   // LDS.64: two adjacent o
        __half2 wv0 = *reinterpret_cast<__half2*>(&wbits);
        __half2 wv1 = *(reinterpret_cast<__half2*>(&wbits) + 1);
        __half2 x0 = xr0[k2];
        __half2 x1 = xr1[k2];
        a00 = __hmax2(a00, __hmin2(x0, wv0));
        a01 = __hmax2(a01, __hmin2(x0, wv1));
        a10 = __hmax2(a10, __hmin2(x1, wv0));
        a11 = __hmax2(a11, __hmin2(x1, wv1));
    }

    // ---- epilogue: reduce packed K-lanes, store float2 per b row ----
    float r00 = fmaxf(__low2float(a00), __high2float(a00));
    float r01 = fmaxf(__low2float(a01), __high2float(a01));
    float r10 = fmaxf(__low2float(a10), __high2float(a10));
    float r11 = fmaxf(__low2float(a11), __high2float(a11));

    float2* o0 = reinterpret_cast<float2*>(out + (size_t)(bB + 2 * ty) * ODIM + oB + 2 * tx);
    float2* o1 = reinterpret_cast<float2*>(out + (size_t)(bB + 2 * ty + 1) * ODIM + oB + 2 * tx);
    *o0 = make_float2(r00, r01);
    *o1 = make_float2(r10, r11);
}

extern "C" void kernel_launch(void* const* d_in, const int* in_sizes, int n_in,
                              void* d_out, int out_size)
{
    const float* x = (const float*)d_in[0];   // [B, 512]
    const float* w = (const float*)d_in[1];   // [512, 512]
    float* out = (float*)d_out;

    int B = in_sizes[0] / KDIM;               // 1024

    int ncv = (B * K2 > K2 * ODIM) ? B * K2 : K2 * ODIM;
    prepack_kernel<<<(ncv + 255) / 256, 256>>>(x, w, B);

    const int smem_bytes = (TB * K2 + K2 * TO) * (int)sizeof(__half2);  // 96 KB
    cudaFuncSetAttribute(maxmin_main_kernel,
                         cudaFuncAttributeMaxDynamicSharedMemorySize, smem_bytes);

    dim3 grid(ODIM / TO, B / TB);             // (16, 16) = 256 blocks
    maxmin_main_kernel<<<grid, NT, smem_bytes>>>(out);
}